// round 12
// baseline (speedup 1.0000x reference)
#include <cuda_runtime.h>
#include <cuda_fp16.h>
#include <math.h>

#define NN   100000
#define EE   1600000
#define FIN  256
#define H1   64
#define H2   128
#define BJ   4096
#define NSCANB ((NN + 1023) / 1024)   // 98
#define G1B   ((NN + 63) / 64)        // 1563 gemm blocks
#define HISTB (EE / 512)              // 3125 hist blocks (2 edges/thread)

// ---------------- scratch (device globals) ----------------
__device__ unsigned long long g_pk[NN];       // (count<<32) | fix(sum ew * 2^23)
__device__ unsigned long long g_part[NSCANB]; // lookback: (status<<32)|value
__device__ float  g_dis[NN];
__device__ int    g_rowptr[NN + 1];
__device__ __align__(8) int g_pos[EE];
__device__ __align__(16) int2 g_edge[EE];     // (src, ew*dis[src]) grouped by dst
__device__ __half  g_wh16[FIN * H1];          // W1 in fp16 [256][64]
__device__ __half2 g_xh1[NN * (H1 / 2)];      // x @ W1 in fp16  [N,64]
__device__ float  g_p[NN];                    // h1[n] . wf
__device__ float  g_wf[H1];                   // wf = W2 @ Wl
__device__ float  g_c;                        // b2.Wl + bl

// ---------------- init: zero pk/part, convert W1->fp16, compute wf/c ----------------
__global__ void k_init(const float* __restrict__ W1, const float* __restrict__ W2,
                       const float* __restrict__ b2, const float* __restrict__ Wl,
                       const float* __restrict__ bl) {
    int i = blockIdx.x * 256 + threadIdx.x;
    if (i < NN) g_pk[i] = 0ull;
    if (i < NSCANB) g_part[i] = 0ull;
    if (i < FIN * H1) g_wh16[i] = __float2half(W1[i]);
    if (blockIdx.x == 0) {
        __shared__ float sWl[H2];
        __shared__ float red[H2];
        int t = threadIdx.x;
        if (t < H2) sWl[t] = Wl[t];
        __syncthreads();
        if (t < H1) {
            float s = 0.f;
#pragma unroll 8
            for (int m = 0; m < H2; m++) s += W2[t * H2 + m] * sWl[m];
            g_wf[t] = s;
        }
        if (t < H2) red[t] = b2[t] * sWl[t];
        __syncthreads();
        if (t == 0) {
            float s = 0.f;
            for (int m = 0; m < H2; m++) s += red[m];
            g_c = s + bl[0];
        }
    }
}

// ---------------- fat kernel: gemm1 (blocks < G1B) + hist (rest) ----------------
// gemm: CTA = 64 rows x 64 cols, 8 warps (4 row-groups x 2 n-groups), tensor mma.
// A: x fp32->fp16 smem [64][264]; B: g_wh16 copied to smem [256][72].
#define A_STRIDE 264
#define B_STRIDE 72
#define FAT_SMEM_BYTES (64 * A_STRIDE * 2 + FIN * B_STRIDE * 2)   // 70656
__global__ void __launch_bounds__(256, 3) k_fat(const float* __restrict__ x,
                                                const int* __restrict__ dst,
                                                const float* __restrict__ ew) {
    if (blockIdx.x >= G1B) {
        // ---------- hist: 2 edges per thread ----------
        int pi = (blockIdx.x - G1B) * 256 + threadIdx.x;   // pair index
        int2  d2 = __ldg(&((const int2*)dst)[pi]);
        float2 w2 = __ldg(&((const float2*)ew)[pi]);
        unsigned int f0 = __float2uint_rn(w2.x * 8388608.0f);
        unsigned int f1 = __float2uint_rn(w2.y * 8388608.0f);
        unsigned long long o0 =
            atomicAdd(&g_pk[d2.x], (1ull << 32) | (unsigned long long)f0);
        unsigned long long o1 =
            atomicAdd(&g_pk[d2.y], (1ull << 32) | (unsigned long long)f1);
        ((int2*)g_pos)[pi] = make_int2((int)(o0 >> 32), (int)(o1 >> 32));
        return;
    }

    // ---------- gemm ----------
    extern __shared__ __half smh[];
    __half* sA = smh;                        // [64][A_STRIDE]
    __half* sB = smh + 64 * A_STRIDE;        // [256][B_STRIDE]
    const int t = threadIdx.x;
    const int lane = t & 31, warp = t >> 5;
    const int rb = blockIdx.x * 64;

    // stage W (fp16 packed -> padded smem): 2048 uint4, 8 iters
    const uint4* WH = (const uint4*)g_wh16;  // 8 halfs each, 8 per k-row
#pragma unroll
    for (int it = 0; it < 8; it++) {
        int idx = t + it * 256;
        int k = idx >> 3, j = idx & 7;
        *(uint4*)&sB[k * B_STRIDE + j * 8] = WH[idx];
    }

    // stage x tile fp32 -> fp16: 4096 f4, 16 iters
    const float4* X4 = (const float4*)x;     // 64 f4 per row
#pragma unroll
    for (int it = 0; it < 16; it++) {
        int idx = t + it * 256;              // 0..4095
        int row = idx >> 6, c4 = idx & 63;
        int grow = rb + row; if (grow >= NN) grow = NN - 1;
        float4 v = __ldg(&X4[(size_t)grow * 64 + c4]);
        *(__half2*)&sA[row * A_STRIDE + c4 * 4 + 0] = __floats2half2_rn(v.x, v.y);
        *(__half2*)&sA[row * A_STRIDE + c4 * 4 + 2] = __floats2half2_rn(v.z, v.w);
    }
    __syncthreads();

    // warp mapping: rg = row group (16 rows), ng = n group (32 cols)
    const int rg = warp >> 1, ng = warp & 1;
    const int g = lane >> 3;
    const int row_off = (lane & 7) + ((g & 1) << 3);
    const int col_tile = g >> 1;

    unsigned int aBase;
    {
        const void* p = &sA[(rg * 16 + row_off) * A_STRIDE + col_tile * 8];
        asm("{ .reg .u64 tmp; cvta.to.shared.u64 tmp, %1; cvt.u32.u64 %0, tmp; }"
            : "=r"(aBase) : "l"(p));
    }
    unsigned int bBase;
    {
        const void* p = &sB[row_off * B_STRIDE + ng * 32 + col_tile * 8];
        asm("{ .reg .u64 tmp; cvta.to.shared.u64 tmp, %1; cvt.u32.u64 %0, tmp; }"
            : "=r"(bBase) : "l"(p));
    }

    float acc[4][4];
#pragma unroll
    for (int n = 0; n < 4; n++)
#pragma unroll
        for (int c = 0; c < 4; c++) acc[n][c] = 0.f;

#pragma unroll 4
    for (int kc = 0; kc < FIN / 16; kc++) {
        unsigned int a0, a1, a2, a3;
        asm volatile("ldmatrix.sync.aligned.m8n8.x4.shared.b16 {%0,%1,%2,%3}, [%4];"
                     : "=r"(a0), "=r"(a1), "=r"(a2), "=r"(a3)
                     : "r"(aBase + kc * 32));
#pragma unroll
        for (int np = 0; np < 2; np++) {     // 2 n-octet pairs (16 cols each)
            unsigned int b0, b1, b2, b3;
            asm volatile("ldmatrix.sync.aligned.m8n8.x4.trans.shared.b16 {%0,%1,%2,%3}, [%4];"
                         : "=r"(b0), "=r"(b1), "=r"(b2), "=r"(b3)
                         : "r"(bBase + (kc * 16 * B_STRIDE + np * 16) * 2));
            asm volatile("mma.sync.aligned.m16n8k16.row.col.f32.f16.f16.f32 "
                         "{%0,%1,%2,%3},{%4,%5,%6,%7},{%8,%9},{%0,%1,%2,%3};"
                         : "+f"(acc[2 * np][0]), "+f"(acc[2 * np][1]),
                           "+f"(acc[2 * np][2]), "+f"(acc[2 * np][3])
                         : "r"(a0), "r"(a1), "r"(a2), "r"(a3), "r"(b0), "r"(b1));
            asm volatile("mma.sync.aligned.m16n8k16.row.col.f32.f16.f16.f32 "
                         "{%0,%1,%2,%3},{%4,%5,%6,%7},{%8,%9},{%0,%1,%2,%3};"
                         : "+f"(acc[2 * np + 1][0]), "+f"(acc[2 * np + 1][1]),
                           "+f"(acc[2 * np + 1][2]), "+f"(acc[2 * np + 1][3])
                         : "r"(a0), "r"(a1), "r"(a2), "r"(a3), "r"(b2), "r"(b3));
        }
    }

    // epilogue: 4 local n-octets at global octet ng*4 + o
    const int gr = lane >> 2, gc = lane & 3;
#pragma unroll
    for (int o = 0; o < 4; o++) {
        int r0 = rb + rg * 16 + gr;
        int r1 = r0 + 8;
        int oc = (ng * 4 + o) * 4 + gc;
        __half2 d01 = __floats2half2_rn(acc[o][0], acc[o][1]);
        __half2 d23 = __floats2half2_rn(acc[o][2], acc[o][3]);
        if (r0 < NN) g_xh1[(size_t)r0 * 32 + oc] = d01;
        if (r1 < NN) g_xh1[(size_t)r1 * 32 + oc] = d23;
    }
}

// ---------------- single-pass scan (decoupled lookback) + dis ----------------
__global__ void __launch_bounds__(256) k_scan() {
    __shared__ unsigned int wsum[8];
    __shared__ unsigned int s_bpref;
    const int b = blockIdx.x, t = threadIdx.x;
    const int lane = t & 31, wid = t >> 5;
    const int base = b * 1024 + t * 4;

    unsigned int c[4]; float dl[4];
#pragma unroll
    for (int j = 0; j < 4; j++) {
        int i = base + j;
        unsigned long long pk = (i < NN) ? g_pk[i] : 0ull;
        c[j]  = (unsigned int)(pk >> 32);
        dl[j] = (float)(unsigned int)pk;
    }
    unsigned int t_tot = c[0] + c[1] + c[2] + c[3];
    unsigned int v = t_tot;
#pragma unroll
    for (int o = 1; o < 32; o <<= 1) {
        unsigned int u = __shfl_up_sync(0xffffffffu, v, o);
        if (lane >= o) v += u;
    }
    if (lane == 31) wsum[wid] = v;
    __syncthreads();
    if (t < 8) {
        unsigned int w = wsum[t];
#pragma unroll
        for (int o = 1; o < 8; o <<= 1) {
            unsigned int u = __shfl_up_sync(0xffu, w, o);
            if (t >= o) w += u;
        }
        wsum[t] = w;
    }
    __syncthreads();
    unsigned int wpref  = (wid > 0) ? wsum[wid - 1] : 0u;
    unsigned int t_excl = wpref + v - t_tot;
    unsigned int btot   = wsum[7];

    if (t == 0) {
        if (b > 0) {
            atomicExch(&g_part[b], (1ull << 32) | (unsigned long long)btot);
            unsigned int excl = 0;
            int pb = b - 1;
            while (true) {
                unsigned long long st = atomicAdd(&g_part[pb], 0ull);
                unsigned int status = (unsigned int)(st >> 32);
                if (status == 2u) { excl += (unsigned int)st; break; }
                if (status == 1u) { excl += (unsigned int)st; pb--; }
            }
            s_bpref = excl;
            atomicExch(&g_part[b], (2ull << 32) | (unsigned long long)(excl + btot));
        } else {
            s_bpref = 0u;
            atomicExch(&g_part[0], (2ull << 32) | (unsigned long long)btot);
        }
    }
    __syncthreads();
    unsigned int run = s_bpref + t_excl;
#pragma unroll
    for (int j = 0; j < 4; j++) {
        int i = base + j;
        if (i < NN) {
            g_rowptr[i] = (int)run;
            g_dis[i] = rsqrtf(1.0f + dl[j] * (1.0f / 8388608.0f));
        }
        run += c[j];
    }
    if (b == NSCANB - 1 && t == 255) g_rowptr[NN] = EE;
}

// ---------------- fill: no atomics, 2 edges/thread ----------------
__global__ void k_fill(const int* __restrict__ src, const int* __restrict__ dst,
                       const float* __restrict__ ew) {
    int pi = blockIdx.x * blockDim.x + threadIdx.x;
    int2   s2 = __ldg(&((const int2*)src)[pi]);
    int2   d2 = __ldg(&((const int2*)dst)[pi]);
    float2 w2 = __ldg(&((const float2*)ew)[pi]);
    int2   p2 = __ldg(&((const int2*)g_pos)[pi]);
    g_edge[g_rowptr[d2.x] + p2.x] = make_int2(s2.x, __float_as_int(w2.x * g_dis[s2.x]));
    g_edge[g_rowptr[d2.y] + p2.y] = make_int2(s2.y, __float_as_int(w2.y * g_dis[s2.y]));
}

// -------- agg1q: warp per node; fp16 rows --------
__global__ void k_agg1q(const float* __restrict__ b1) {
    int warp = (blockIdx.x * blockDim.x + threadIdx.x) >> 5;
    int lane = threadIdx.x & 31;
    if (warp >= NN) return;
    const int node = warp;
    int beg = g_rowptr[node], end = g_rowptr[node + 1];
    float2 v = make_float2(0.f, 0.f);
    const __half2* XH = g_xh1;

    int i = beg;
    if ((i & 1) && i < end) {
        int2 e = __ldg(&g_edge[i]);
        float w = __int_as_float(e.y);
        float2 a = __half22float2(__ldg(&XH[(size_t)e.x * 32 + lane]));
        v.x += w * a.x; v.y += w * a.y;
        i++;
    }
    for (; i + 1 < end; i += 2) {
        int4 ee = __ldg((const int4*)&g_edge[i]);
        float w0 = __int_as_float(ee.y), w1 = __int_as_float(ee.w);
        float2 a = __half22float2(__ldg(&XH[(size_t)ee.x * 32 + lane]));
        float2 b = __half22float2(__ldg(&XH[(size_t)ee.z * 32 + lane]));
        v.x += w0 * a.x + w1 * b.x;
        v.y += w0 * a.y + w1 * b.y;
    }
    if (i < end) {
        int2 e = __ldg(&g_edge[i]);
        float w = __int_as_float(e.y);
        float2 a = __half22float2(__ldg(&XH[(size_t)e.x * 32 + lane]));
        v.x += w * a.x; v.y += w * a.y;
    }

    float d = g_dis[node];
    float2 sv = __half22float2(XH[(size_t)node * 32 + lane]);
    float2 bb = __ldg(&((const float2*)b1)[lane]);
    float hx = fmaxf(fmaf(d, fmaf(d, sv.x, v.x), bb.x), 0.f);
    float hy = fmaxf(fmaf(d, fmaf(d, sv.y, v.y), bb.y), 0.f);
    float2 wf = ((const float2*)g_wf)[lane];
    float s = hx * wf.x + hy * wf.y;
#pragma unroll
    for (int o = 16; o > 0; o >>= 1) s += __shfl_down_sync(0xffffffffu, s, o);
    if (lane == 0) g_p[node] = s;
}

// ---------------- head ----------------
__global__ void k_head(const int* __restrict__ join, float* __restrict__ out) {
    int warp = (blockIdx.x * blockDim.x + threadIdx.x) >> 5;
    int lane = threadIdx.x & 31;
    if (warp >= BJ) return;
    int j = join[warp];
    int beg = g_rowptr[j], end = g_rowptr[j + 1];
    float acc = 0.f;
    for (int i = beg + lane; i < end; i += 32) {
        int2 e = __ldg(&g_edge[i]);
        acc += __int_as_float(e.y) * __ldg(&g_p[e.x]);
    }
#pragma unroll
    for (int o = 16; o > 0; o >>= 1) acc += __shfl_down_sync(0xffffffffu, acc, o);
    if (lane == 0) {
        float d = g_dis[j];
        float z = d * fmaf(d, g_p[j], acc) + g_c;
        out[warp] = 1.0f / (1.0f + expf(-z));
    }
}

// ---------------- launch ----------------
extern "C" void kernel_launch(void* const* d_in, const int* in_sizes, int n_in,
                              void* d_out, int out_size) {
    (void)in_sizes; (void)n_in; (void)out_size;
    const float* x    = (const float*)d_in[0];
    const int*   eidx = (const int*)  d_in[1];
    const int*   join = (const int*)  d_in[2];
    const float* ew   = (const float*)d_in[3];
    const float* W1   = (const float*)d_in[4];
    const float* b1   = (const float*)d_in[5];
    const float* W2   = (const float*)d_in[6];
    const float* b2   = (const float*)d_in[7];
    const float* Wl   = (const float*)d_in[8];
    const float* bl   = (const float*)d_in[9];
    float*       out  = (float*)d_out;

    const int* src = eidx;
    const int* dst = eidx + EE;

    static bool inited = false;
    if (!inited) {
        cudaFuncSetAttribute(k_fat, cudaFuncAttributeMaxDynamicSharedMemorySize,
                             FAT_SMEM_BYTES);
        inited = true;
    }

    k_init  <<<(NN + 255) / 256, 256>>>(W1, W2, b2, Wl, bl);       // #0
    k_fat   <<<G1B + HISTB, 256, FAT_SMEM_BYTES>>>(x, dst, ew);    // #1
    k_scan  <<<NSCANB, 256>>>();                                   // #2
    k_fill  <<<HISTB, 256>>>(src, dst, ew);                        // #3 <- profiled
    k_agg1q <<<(NN * 32 + 255) / 256, 256>>>(b1);                  // #4
    k_head  <<<(BJ * 32) / 256, 256>>>(join, out);                 // #5
}

// round 13
// speedup vs baseline: 1.0423x; 1.0423x over previous
#include <cuda_runtime.h>
#include <cuda_fp16.h>
#include <math.h>

#define NN   100000
#define EE   1600000
#define FIN  256
#define H1   64
#define H2   128
#define BJ   4096
#define NSCANB ((NN + 1023) / 1024)   // 98
#define HISTB (EE / 512)              // 3125 (2 edges/thread)

// ---------------- scratch (device globals) ----------------
__device__ unsigned long long g_pk[NN];       // (count<<32) | fix(sum ew * 2^23)
__device__ unsigned long long g_part[NSCANB]; // lookback: (status<<32)|value
__device__ float  g_dis[NN];
__device__ int    g_rowptr[NN + 1];
__device__ __align__(8) int g_pos[EE];
__device__ __align__(16) int2 g_edge[EE];     // (src, ew*dis[src]) grouped by dst
__device__ __half2 g_xh1[NN * (H1 / 2)];      // x @ W1 in fp16  [N,64]
__device__ float  g_p[NN];                    // h1[n] . wf
__device__ float  g_wf[H1];                   // wf = W2 @ Wl
__device__ float  g_c;                        // b2.Wl + bl

// ---------------- init: zero pk/part + wf + c ----------------
__global__ void k_init(const float* __restrict__ W2, const float* __restrict__ b2,
                       const float* __restrict__ Wl, const float* __restrict__ bl) {
    int i = blockIdx.x * 256 + threadIdx.x;
    if (i < NN) g_pk[i] = 0ull;
    if (i < NSCANB) g_part[i] = 0ull;
    if (blockIdx.x == 0) {
        __shared__ float sWl[H2];
        __shared__ float red[H2];
        int t = threadIdx.x;
        if (t < H2) sWl[t] = Wl[t];
        __syncthreads();
        if (t < H1) {
            float s = 0.f;
#pragma unroll 8
            for (int m = 0; m < H2; m++) s += W2[t * H2 + m] * sWl[m];
            g_wf[t] = s;
        }
        if (t < H2) red[t] = b2[t] * sWl[t];
        __syncthreads();
        if (t == 0) {
            float s = 0.f;
            for (int m = 0; m < H2; m++) s += red[m];
            g_c = s + bl[0];
        }
    }
}

// ---------------- hist: 2 edges/thread, packed atomic ----------------
__global__ void k_hist(const int* __restrict__ dst, const float* __restrict__ ew) {
    int pi = blockIdx.x * blockDim.x + threadIdx.x;
    int2   d2 = __ldg(&((const int2*)dst)[pi]);
    float2 w2 = __ldg(&((const float2*)ew)[pi]);
    unsigned int f0 = __float2uint_rn(w2.x * 8388608.0f);
    unsigned int f1 = __float2uint_rn(w2.y * 8388608.0f);
    unsigned long long o0 =
        atomicAdd(&g_pk[d2.x], (1ull << 32) | (unsigned long long)f0);
    unsigned long long o1 =
        atomicAdd(&g_pk[d2.y], (1ull << 32) | (unsigned long long)f1);
    ((int2*)g_pos)[pi] = make_int2((int)(o0 >> 32), (int)(o1 >> 32));
}

// ---------------- single-pass scan (decoupled lookback) + dis ----------------
__global__ void __launch_bounds__(256) k_scan() {
    __shared__ unsigned int wsum[8];
    __shared__ unsigned int s_bpref;
    const int b = blockIdx.x, t = threadIdx.x;
    const int lane = t & 31, wid = t >> 5;
    const int base = b * 1024 + t * 4;

    unsigned int c[4]; float dl[4];
#pragma unroll
    for (int j = 0; j < 4; j++) {
        int i = base + j;
        unsigned long long pk = (i < NN) ? g_pk[i] : 0ull;
        c[j]  = (unsigned int)(pk >> 32);
        dl[j] = (float)(unsigned int)pk;
    }
    unsigned int t_tot = c[0] + c[1] + c[2] + c[3];
    unsigned int v = t_tot;
#pragma unroll
    for (int o = 1; o < 32; o <<= 1) {
        unsigned int u = __shfl_up_sync(0xffffffffu, v, o);
        if (lane >= o) v += u;
    }
    if (lane == 31) wsum[wid] = v;
    __syncthreads();
    if (t < 8) {
        unsigned int w = wsum[t];
#pragma unroll
        for (int o = 1; o < 8; o <<= 1) {
            unsigned int u = __shfl_up_sync(0xffu, w, o);
            if (t >= o) w += u;
        }
        wsum[t] = w;
    }
    __syncthreads();
    unsigned int wpref  = (wid > 0) ? wsum[wid - 1] : 0u;
    unsigned int t_excl = wpref + v - t_tot;
    unsigned int btot   = wsum[7];

    if (t == 0) {
        if (b > 0) {
            atomicExch(&g_part[b], (1ull << 32) | (unsigned long long)btot);
            unsigned int excl = 0;
            int pb = b - 1;
            while (true) {
                unsigned long long st = atomicAdd(&g_part[pb], 0ull);
                unsigned int status = (unsigned int)(st >> 32);
                if (status == 2u) { excl += (unsigned int)st; break; }
                if (status == 1u) { excl += (unsigned int)st; pb--; }
            }
            s_bpref = excl;
            atomicExch(&g_part[b], (2ull << 32) | (unsigned long long)(excl + btot));
        } else {
            s_bpref = 0u;
            atomicExch(&g_part[0], (2ull << 32) | (unsigned long long)btot);
        }
    }
    __syncthreads();
    unsigned int run = s_bpref + t_excl;
#pragma unroll
    for (int j = 0; j < 4; j++) {
        int i = base + j;
        if (i < NN) {
            g_rowptr[i] = (int)run;
            g_dis[i] = rsqrtf(1.0f + dl[j] * (1.0f / 8388608.0f));
        }
        run += c[j];
    }
    if (b == NSCANB - 1 && t == 255) g_rowptr[NN] = EE;
}

// ---------------- fill: no atomics, 2 edges/thread ----------------
__global__ void k_fill(const int* __restrict__ src, const int* __restrict__ dst,
                       const float* __restrict__ ew) {
    int pi = blockIdx.x * blockDim.x + threadIdx.x;
    int2   s2 = __ldg(&((const int2*)src)[pi]);
    int2   d2 = __ldg(&((const int2*)dst)[pi]);
    float2 w2 = __ldg(&((const float2*)ew)[pi]);
    int2   p2 = __ldg(&((const int2*)g_pos)[pi]);
    g_edge[g_rowptr[d2.x] + p2.x] = make_int2(s2.x, __float_as_int(w2.x * g_dis[s2.x]));
    g_edge[g_rowptr[d2.y] + p2.y] = make_int2(s2.y, __float_as_int(w2.y * g_dis[s2.y]));
}

// ---------------- GEMM1 (tensor core): xh1 = fp16(x @ W1) ----------------
// 256 thr, CTA = 64 rows x 64 cols, 8 warps (4 row-groups x 2 n-groups).
// smem 70.6KB -> 3 CTAs/SM.
#define A_STRIDE 264
#define B_STRIDE 72
#define G1_SMEM_BYTES (64 * A_STRIDE * 2 + FIN * B_STRIDE * 2)   // 70656
__global__ void __launch_bounds__(256, 3) k_gemm1(const float* __restrict__ x,
                                                  const float* __restrict__ W1) {
    extern __shared__ __half smh[];
    __half* sA = smh;                        // [64][A_STRIDE]
    __half* sB = smh + 64 * A_STRIDE;        // [256][B_STRIDE]
    const int t = threadIdx.x;
    const int lane = t & 31, warp = t >> 5;
    const int rb = blockIdx.x * 64;

    // stage W1 fp32 -> fp16: 4096 f4, 16 iters
    const float4* W4 = (const float4*)W1;
#pragma unroll
    for (int it = 0; it < 16; it++) {
        int idx = t + it * 256;
        int k = idx >> 4, n4 = idx & 15;
        float4 w = W4[idx];
        *(__half2*)&sB[k * B_STRIDE + n4 * 4 + 0] = __floats2half2_rn(w.x, w.y);
        *(__half2*)&sB[k * B_STRIDE + n4 * 4 + 2] = __floats2half2_rn(w.z, w.w);
    }

    // stage x tile fp32 -> fp16: 4096 f4, 16 iters
    const float4* X4 = (const float4*)x;
#pragma unroll
    for (int it = 0; it < 16; it++) {
        int idx = t + it * 256;              // 0..4095
        int row = idx >> 6, c4 = idx & 63;
        int grow = rb + row; if (grow >= NN) grow = NN - 1;
        float4 v = __ldg(&X4[(size_t)grow * 64 + c4]);
        *(__half2*)&sA[row * A_STRIDE + c4 * 4 + 0] = __floats2half2_rn(v.x, v.y);
        *(__half2*)&sA[row * A_STRIDE + c4 * 4 + 2] = __floats2half2_rn(v.z, v.w);
    }
    __syncthreads();

    // warp mapping: rg = row group (16 rows), ng = n group (32 cols)
    const int rg = warp >> 1, ng = warp & 1;
    const int g = lane >> 3;
    const int row_off = (lane & 7) + ((g & 1) << 3);
    const int col_tile = g >> 1;

    unsigned int aBase;
    {
        const void* p = &sA[(rg * 16 + row_off) * A_STRIDE + col_tile * 8];
        asm("{ .reg .u64 tmp; cvta.to.shared.u64 tmp, %1; cvt.u32.u64 %0, tmp; }"
            : "=r"(aBase) : "l"(p));
    }
    unsigned int bBase;
    {
        const void* p = &sB[row_off * B_STRIDE + ng * 32 + col_tile * 8];
        asm("{ .reg .u64 tmp; cvta.to.shared.u64 tmp, %1; cvt.u32.u64 %0, tmp; }"
            : "=r"(bBase) : "l"(p));
    }

    float acc[4][4];
#pragma unroll
    for (int n = 0; n < 4; n++)
#pragma unroll
        for (int c = 0; c < 4; c++) acc[n][c] = 0.f;

#pragma unroll 4
    for (int kc = 0; kc < FIN / 16; kc++) {
        unsigned int a0, a1, a2, a3;
        asm volatile("ldmatrix.sync.aligned.m8n8.x4.shared.b16 {%0,%1,%2,%3}, [%4];"
                     : "=r"(a0), "=r"(a1), "=r"(a2), "=r"(a3)
                     : "r"(aBase + kc * 32));
#pragma unroll
        for (int np = 0; np < 2; np++) {
            unsigned int b0, b1, b2, b3;
            asm volatile("ldmatrix.sync.aligned.m8n8.x4.trans.shared.b16 {%0,%1,%2,%3}, [%4];"
                         : "=r"(b0), "=r"(b1), "=r"(b2), "=r"(b3)
                         : "r"(bBase + (kc * 16 * B_STRIDE + np * 16) * 2));
            asm volatile("mma.sync.aligned.m16n8k16.row.col.f32.f16.f16.f32 "
                         "{%0,%1,%2,%3},{%4,%5,%6,%7},{%8,%9},{%0,%1,%2,%3};"
                         : "+f"(acc[2 * np][0]), "+f"(acc[2 * np][1]),
                           "+f"(acc[2 * np][2]), "+f"(acc[2 * np][3])
                         : "r"(a0), "r"(a1), "r"(a2), "r"(a3), "r"(b0), "r"(b1));
            asm volatile("mma.sync.aligned.m16n8k16.row.col.f32.f16.f16.f32 "
                         "{%0,%1,%2,%3},{%4,%5,%6,%7},{%8,%9},{%0,%1,%2,%3};"
                         : "+f"(acc[2 * np + 1][0]), "+f"(acc[2 * np + 1][1]),
                           "+f"(acc[2 * np + 1][2]), "+f"(acc[2 * np + 1][3])
                         : "r"(a0), "r"(a1), "r"(a2), "r"(a3), "r"(b2), "r"(b3));
        }
    }

    // epilogue: 4 local n-octets at global octet ng*4 + o
    const int gr = lane >> 2, gc = lane & 3;
#pragma unroll
    for (int o = 0; o < 4; o++) {
        int r0 = rb + rg * 16 + gr;
        int r1 = r0 + 8;
        int oc = (ng * 4 + o) * 4 + gc;
        __half2 d01 = __floats2half2_rn(acc[o][0], acc[o][1]);
        __half2 d23 = __floats2half2_rn(acc[o][2], acc[o][3]);
        if (r0 < NN) g_xh1[(size_t)r0 * 32 + oc] = d01;
        if (r1 < NN) g_xh1[(size_t)r1 * 32 + oc] = d23;
    }
}

// -------- agg1q: warp per node; fp16 rows --------
__global__ void k_agg1q(const float* __restrict__ b1) {
    int warp = (blockIdx.x * blockDim.x + threadIdx.x) >> 5;
    int lane = threadIdx.x & 31;
    if (warp >= NN) return;
    const int node = warp;
    int beg = g_rowptr[node], end = g_rowptr[node + 1];
    float2 v = make_float2(0.f, 0.f);
    const __half2* XH = g_xh1;

    int i = beg;
    if ((i & 1) && i < end) {
        int2 e = __ldg(&g_edge[i]);
        float w = __int_as_float(e.y);
        float2 a = __half22float2(__ldg(&XH[(size_t)e.x * 32 + lane]));
        v.x += w * a.x; v.y += w * a.y;
        i++;
    }
    for (; i + 1 < end; i += 2) {
        int4 ee = __ldg((const int4*)&g_edge[i]);
        float w0 = __int_as_float(ee.y), w1 = __int_as_float(ee.w);
        float2 a = __half22float2(__ldg(&XH[(size_t)ee.x * 32 + lane]));
        float2 b = __half22float2(__ldg(&XH[(size_t)ee.z * 32 + lane]));
        v.x += w0 * a.x + w1 * b.x;
        v.y += w0 * a.y + w1 * b.y;
    }
    if (i < end) {
        int2 e = __ldg(&g_edge[i]);
        float w = __int_as_float(e.y);
        float2 a = __half22float2(__ldg(&XH[(size_t)e.x * 32 + lane]));
        v.x += w * a.x; v.y += w * a.y;
    }

    float d = g_dis[node];
    float2 sv = __half22float2(XH[(size_t)node * 32 + lane]);
    float2 bb = __ldg(&((const float2*)b1)[lane]);
    float hx = fmaxf(fmaf(d, fmaf(d, sv.x, v.x), bb.x), 0.f);
    float hy = fmaxf(fmaf(d, fmaf(d, sv.y, v.y), bb.y), 0.f);
    float2 wf = ((const float2*)g_wf)[lane];
    float s = hx * wf.x + hy * wf.y;
#pragma unroll
    for (int o = 16; o > 0; o >>= 1) s += __shfl_down_sync(0xffffffffu, s, o);
    if (lane == 0) g_p[node] = s;
}

// ---------------- head ----------------
__global__ void k_head(const int* __restrict__ join, float* __restrict__ out) {
    int warp = (blockIdx.x * blockDim.x + threadIdx.x) >> 5;
    int lane = threadIdx.x & 31;
    if (warp >= BJ) return;
    int j = join[warp];
    int beg = g_rowptr[j], end = g_rowptr[j + 1];
    float acc = 0.f;
    for (int i = beg + lane; i < end; i += 32) {
        int2 e = __ldg(&g_edge[i]);
        acc += __int_as_float(e.y) * __ldg(&g_p[e.x]);
    }
#pragma unroll
    for (int o = 16; o > 0; o >>= 1) acc += __shfl_down_sync(0xffffffffu, acc, o);
    if (lane == 0) {
        float d = g_dis[j];
        float z = d * fmaf(d, g_p[j], acc) + g_c;
        out[warp] = 1.0f / (1.0f + expf(-z));
    }
}

// ---------------- launch ----------------
extern "C" void kernel_launch(void* const* d_in, const int* in_sizes, int n_in,
                              void* d_out, int out_size) {
    (void)in_sizes; (void)n_in; (void)out_size;
    const float* x    = (const float*)d_in[0];
    const int*   eidx = (const int*)  d_in[1];
    const int*   join = (const int*)  d_in[2];
    const float* ew   = (const float*)d_in[3];
    const float* W1   = (const float*)d_in[4];
    const float* b1   = (const float*)d_in[5];
    const float* W2   = (const float*)d_in[6];
    const float* b2   = (const float*)d_in[7];
    const float* Wl   = (const float*)d_in[8];
    const float* bl   = (const float*)d_in[9];
    float*       out  = (float*)d_out;

    const int* src = eidx;
    const int* dst = eidx + EE;

    static cudaStream_t sA = 0;
    static cudaEvent_t evRoot = 0, evA = 0;
    static bool inited = false;
    if (!inited) {
        cudaStreamCreateWithFlags(&sA, cudaStreamNonBlocking);
        cudaEventCreateWithFlags(&evRoot, cudaEventDisableTiming);
        cudaEventCreateWithFlags(&evA, cudaEventDisableTiming);
        cudaFuncSetAttribute(k_gemm1, cudaFuncAttributeMaxDynamicSharedMemorySize,
                             G1_SMEM_BYTES);
        inited = true;
    }

    const int g1_blocks = (NN + 63) / 64;             // 1563

    cudaEventRecord(evRoot, 0);
    cudaStreamWaitEvent(sA, evRoot, 0);

    k_init  <<<(NN + 255) / 256, 256>>>(W2, b2, Wl, bl);           // #0 (B)
    k_hist  <<<HISTB, 256>>>(dst, ew);                             // #1 (B)
    k_scan  <<<NSCANB, 256>>>();                                   // #2 (B)
    k_gemm1 <<<g1_blocks, 256, G1_SMEM_BYTES, sA>>>(x, W1);        // #3 (A) <- profiled
    k_fill  <<<HISTB, 256>>>(src, dst, ew);                        // #4 (B)

    cudaEventRecord(evA, sA);
    cudaStreamWaitEvent(0, evA, 0);                                // join A -> B

    k_agg1q <<<(NN * 32 + 255) / 256, 256>>>(b1);                  // #5
    k_head  <<<(BJ * 32) / 256, 256>>>(join, out);                 // #6
}

// round 14
// speedup vs baseline: 1.0824x; 1.0385x over previous
#include <cuda_runtime.h>
#include <cuda_fp16.h>
#include <math.h>

#define NN   100000
#define EE   1600000
#define FIN  256
#define H1   64
#define H2   128
#define BJ   4096
#define NSCANB ((NN + 1023) / 1024)   // 98

// ---------------- scratch (device globals) ----------------
__device__ unsigned long long g_pk[NN];       // (count<<32) | fix(sum ew * 2^23)
__device__ unsigned long long g_part[NSCANB]; // lookback: (status<<32)|value
__device__ float  g_dis[NN];
__device__ int    g_rowptr[NN + 1];
__device__ int    g_pos[EE];
__device__ __align__(16) int2 g_edge[EE];     // (src, ew*dis[src]) grouped by dst
__device__ __half2 g_xh1[NN * (H1 / 2)];      // x @ W1 in fp16  [N,64]
__device__ float  g_p[NN];                    // h1[n] . wf
__device__ float  g_wf[H1];                   // wf = W2 @ Wl
__device__ float  g_c;                        // b2.Wl + bl

// ---------------- init: zero pk/part + wf + c ----------------
__global__ void k_init(const float* __restrict__ W2, const float* __restrict__ b2,
                       const float* __restrict__ Wl, const float* __restrict__ bl) {
    int i = blockIdx.x * 256 + threadIdx.x;
    if (i < NN) g_pk[i] = 0ull;
    if (i < NSCANB) g_part[i] = 0ull;
    if (blockIdx.x == 0) {
        __shared__ float sWl[H2];
        __shared__ float red[H2];
        int t = threadIdx.x;
        if (t < H2) sWl[t] = Wl[t];
        __syncthreads();
        if (t < H1) {
            float s = 0.f;
#pragma unroll 8
            for (int m = 0; m < H2; m++) s += W2[t * H2 + m] * sWl[m];
            g_wf[t] = s;
        }
        if (t < H2) red[t] = b2[t] * sWl[t];
        __syncthreads();
        if (t == 0) {
            float s = 0.f;
            for (int m = 0; m < H2; m++) s += red[m];
            g_c = s + bl[0];
        }
    }
}

// ---------------- hist: 1 edge/thread, packed atomic; position for free ----------------
__global__ void k_hist(const int* __restrict__ dst, const float* __restrict__ ew) {
    int e = blockIdx.x * blockDim.x + threadIdx.x;
    if (e < EE) {
        int d = dst[e];
        unsigned int fx = __float2uint_rn(ew[e] * 8388608.0f);
        unsigned long long old =
            atomicAdd(&g_pk[d], (1ull << 32) | (unsigned long long)fx);
        g_pos[e] = (int)(old >> 32);
    }
}

// ---------------- single-pass scan (decoupled lookback) + dis ----------------
__global__ void __launch_bounds__(256) k_scan() {
    __shared__ unsigned int wsum[8];
    __shared__ unsigned int s_bpref;
    const int b = blockIdx.x, t = threadIdx.x;
    const int lane = t & 31, wid = t >> 5;
    const int base = b * 1024 + t * 4;

    unsigned int c[4]; float dl[4];
#pragma unroll
    for (int j = 0; j < 4; j++) {
        int i = base + j;
        unsigned long long pk = (i < NN) ? g_pk[i] : 0ull;
        c[j]  = (unsigned int)(pk >> 32);
        dl[j] = (float)(unsigned int)pk;
    }
    unsigned int t_tot = c[0] + c[1] + c[2] + c[3];
    unsigned int v = t_tot;
#pragma unroll
    for (int o = 1; o < 32; o <<= 1) {
        unsigned int u = __shfl_up_sync(0xffffffffu, v, o);
        if (lane >= o) v += u;
    }
    if (lane == 31) wsum[wid] = v;
    __syncthreads();
    if (t < 8) {
        unsigned int w = wsum[t];
#pragma unroll
        for (int o = 1; o < 8; o <<= 1) {
            unsigned int u = __shfl_up_sync(0xffu, w, o);
            if (t >= o) w += u;
        }
        wsum[t] = w;
    }
    __syncthreads();
    unsigned int wpref  = (wid > 0) ? wsum[wid - 1] : 0u;
    unsigned int t_excl = wpref + v - t_tot;
    unsigned int btot   = wsum[7];

    if (t == 0) {
        if (b > 0) {
            atomicExch(&g_part[b], (1ull << 32) | (unsigned long long)btot);
            unsigned int excl = 0;
            int pb = b - 1;
            while (true) {
                unsigned long long st = atomicAdd(&g_part[pb], 0ull);
                unsigned int status = (unsigned int)(st >> 32);
                if (status == 2u) { excl += (unsigned int)st; break; }
                if (status == 1u) { excl += (unsigned int)st; pb--; }
            }
            s_bpref = excl;
            atomicExch(&g_part[b], (2ull << 32) | (unsigned long long)(excl + btot));
        } else {
            s_bpref = 0u;
            atomicExch(&g_part[0], (2ull << 32) | (unsigned long long)btot);
        }
    }
    __syncthreads();
    unsigned int run = s_bpref + t_excl;
#pragma unroll
    for (int j = 0; j < 4; j++) {
        int i = base + j;
        if (i < NN) {
            g_rowptr[i] = (int)run;
            g_dis[i] = rsqrtf(1.0f + dl[j] * (1.0f / 8388608.0f));
        }
        run += c[j];
    }
    if (b == NSCANB - 1 && t == 255) g_rowptr[NN] = EE;
}

// ---------------- fill: no atomics, 1 edge/thread ----------------
__global__ void k_fill(const int* __restrict__ src, const int* __restrict__ dst,
                       const float* __restrict__ ew) {
    int e = blockIdx.x * blockDim.x + threadIdx.x;
    if (e < EE) {
        int d = dst[e];
        int s = src[e];
        int p = g_rowptr[d] + g_pos[e];
        g_edge[p] = make_int2(s, __float_as_int(ew[e] * g_dis[s]));
    }
}

// ---------------- GEMM1 (tensor core): xh1 = fp16(x @ W1) ----------------
// 512 thr (16 warps), CTA = 128 rows x 64 cols; warp tile 16x32.
// smem 104448 B -> 2 CTAs/SM, 32 warps/SM.
#define A_STRIDE 264
#define B_STRIDE 72
#define G1_SMEM_BYTES (128 * A_STRIDE * 2 + FIN * B_STRIDE * 2)   // 104448
__global__ void __launch_bounds__(512, 2) k_gemm1(const float* __restrict__ x,
                                                  const float* __restrict__ W1) {
    extern __shared__ __half smh[];
    __half* sA = smh;                        // [128][A_STRIDE]
    __half* sB = smh + 128 * A_STRIDE;       // [256][B_STRIDE]
    const int t = threadIdx.x;
    const int lane = t & 31, warp = t >> 5;
    const int rb = blockIdx.x * 128;

    // stage W1 fp32 -> fp16: 4096 f4, 8 iters
    const float4* W4 = (const float4*)W1;
#pragma unroll
    for (int it = 0; it < 8; it++) {
        int idx = t + it * 512;
        int k = idx >> 4, n4 = idx & 15;
        float4 w = W4[idx];
        *(__half2*)&sB[k * B_STRIDE + n4 * 4 + 0] = __floats2half2_rn(w.x, w.y);
        *(__half2*)&sB[k * B_STRIDE + n4 * 4 + 2] = __floats2half2_rn(w.z, w.w);
    }

    // stage x tile fp32 -> fp16: 8192 f4, 16 iters
    const float4* X4 = (const float4*)x;
#pragma unroll
    for (int it = 0; it < 16; it++) {
        int idx = t + it * 512;              // 0..8191
        int row = idx >> 6, c4 = idx & 63;
        int grow = rb + row; if (grow >= NN) grow = NN - 1;
        float4 v = __ldg(&X4[(size_t)grow * 64 + c4]);
        *(__half2*)&sA[row * A_STRIDE + c4 * 4 + 0] = __floats2half2_rn(v.x, v.y);
        *(__half2*)&sA[row * A_STRIDE + c4 * 4 + 2] = __floats2half2_rn(v.z, v.w);
    }
    __syncthreads();

    // warp mapping: rg = row group (16 rows, 0..7), ng = n group (32 cols, 0..1)
    const int rg = warp >> 1, ng = warp & 1;
    const int g = lane >> 3;
    const int row_off = (lane & 7) + ((g & 1) << 3);
    const int col_tile = g >> 1;

    unsigned int aBase;
    {
        const void* p = &sA[(rg * 16 + row_off) * A_STRIDE + col_tile * 8];
        asm("{ .reg .u64 tmp; cvta.to.shared.u64 tmp, %1; cvt.u32.u64 %0, tmp; }"
            : "=r"(aBase) : "l"(p));
    }
    unsigned int bBase;
    {
        const void* p = &sB[row_off * B_STRIDE + ng * 32 + col_tile * 8];
        asm("{ .reg .u64 tmp; cvta.to.shared.u64 tmp, %1; cvt.u32.u64 %0, tmp; }"
            : "=r"(bBase) : "l"(p));
    }

    float acc[4][4];
#pragma unroll
    for (int n = 0; n < 4; n++)
#pragma unroll
        for (int c = 0; c < 4; c++) acc[n][c] = 0.f;

#pragma unroll 4
    for (int kc = 0; kc < FIN / 16; kc++) {
        unsigned int a0, a1, a2, a3;
        asm volatile("ldmatrix.sync.aligned.m8n8.x4.shared.b16 {%0,%1,%2,%3}, [%4];"
                     : "=r"(a0), "=r"(a1), "=r"(a2), "=r"(a3)
                     : "r"(aBase + kc * 32));
#pragma unroll
        for (int np = 0; np < 2; np++) {
            unsigned int b0, b1, b2, b3;
            asm volatile("ldmatrix.sync.aligned.m8n8.x4.trans.shared.b16 {%0,%1,%2,%3}, [%4];"
                         : "=r"(b0), "=r"(b1), "=r"(b2), "=r"(b3)
                         : "r"(bBase + (kc * 16 * B_STRIDE + np * 16) * 2));
            asm volatile("mma.sync.aligned.m16n8k16.row.col.f32.f16.f16.f32 "
                         "{%0,%1,%2,%3},{%4,%5,%6,%7},{%8,%9},{%0,%1,%2,%3};"
                         : "+f"(acc[2 * np][0]), "+f"(acc[2 * np][1]),
                           "+f"(acc[2 * np][2]), "+f"(acc[2 * np][3])
                         : "r"(a0), "r"(a1), "r"(a2), "r"(a3), "r"(b0), "r"(b1));
            asm volatile("mma.sync.aligned.m16n8k16.row.col.f32.f16.f16.f32 "
                         "{%0,%1,%2,%3},{%4,%5,%6,%7},{%8,%9},{%0,%1,%2,%3};"
                         : "+f"(acc[2 * np + 1][0]), "+f"(acc[2 * np + 1][1]),
                           "+f"(acc[2 * np + 1][2]), "+f"(acc[2 * np + 1][3])
                         : "r"(a0), "r"(a1), "r"(a2), "r"(a3), "r"(b2), "r"(b3));
        }
    }

    // epilogue: 4 local n-octets at global octet ng*4 + o
    const int gr = lane >> 2, gc = lane & 3;
#pragma unroll
    for (int o = 0; o < 4; o++) {
        int r0 = rb + rg * 16 + gr;
        int r1 = r0 + 8;
        int oc = (ng * 4 + o) * 4 + gc;
        __half2 d01 = __floats2half2_rn(acc[o][0], acc[o][1]);
        __half2 d23 = __floats2half2_rn(acc[o][2], acc[o][3]);
        if (r0 < NN) g_xh1[(size_t)r0 * 32 + oc] = d01;
        if (r1 < NN) g_xh1[(size_t)r1 * 32 + oc] = d23;
    }
}

// -------- agg1q: warp per node; fp16 rows --------
__global__ void k_agg1q(const float* __restrict__ b1) {
    int warp = (blockIdx.x * blockDim.x + threadIdx.x) >> 5;
    int lane = threadIdx.x & 31;
    if (warp >= NN) return;
    const int node = warp;
    int beg = g_rowptr[node], end = g_rowptr[node + 1];
    float2 v = make_float2(0.f, 0.f);
    const __half2* XH = g_xh1;

    int i = beg;
    if ((i & 1) && i < end) {
        int2 e = __ldg(&g_edge[i]);
        float w = __int_as_float(e.y);
        float2 a = __half22float2(__ldg(&XH[(size_t)e.x * 32 + lane]));
        v.x += w * a.x; v.y += w * a.y;
        i++;
    }
    for (; i + 1 < end; i += 2) {
        int4 ee = __ldg((const int4*)&g_edge[i]);
        float w0 = __int_as_float(ee.y), w1 = __int_as_float(ee.w);
        float2 a = __half22float2(__ldg(&XH[(size_t)ee.x * 32 + lane]));
        float2 b = __half22float2(__ldg(&XH[(size_t)ee.z * 32 + lane]));
        v.x += w0 * a.x + w1 * b.x;
        v.y += w0 * a.y + w1 * b.y;
    }
    if (i < end) {
        int2 e = __ldg(&g_edge[i]);
        float w = __int_as_float(e.y);
        float2 a = __half22float2(__ldg(&XH[(size_t)e.x * 32 + lane]));
        v.x += w * a.x; v.y += w * a.y;
    }

    float d = g_dis[node];
    float2 sv = __half22float2(XH[(size_t)node * 32 + lane]);
    float2 bb = __ldg(&((const float2*)b1)[lane]);
    float hx = fmaxf(fmaf(d, fmaf(d, sv.x, v.x), bb.x), 0.f);
    float hy = fmaxf(fmaf(d, fmaf(d, sv.y, v.y), bb.y), 0.f);
    float2 wf = ((const float2*)g_wf)[lane];
    float s = hx * wf.x + hy * wf.y;
#pragma unroll
    for (int o = 16; o > 0; o >>= 1) s += __shfl_down_sync(0xffffffffu, s, o);
    if (lane == 0) g_p[node] = s;
}

// ---------------- head ----------------
__global__ void k_head(const int* __restrict__ join, float* __restrict__ out) {
    int warp = (blockIdx.x * blockDim.x + threadIdx.x) >> 5;
    int lane = threadIdx.x & 31;
    if (warp >= BJ) return;
    int j = join[warp];
    int beg = g_rowptr[j], end = g_rowptr[j + 1];
    float acc = 0.f;
    for (int i = beg + lane; i < end; i += 32) {
        int2 e = __ldg(&g_edge[i]);
        acc += __int_as_float(e.y) * __ldg(&g_p[e.x]);
    }
#pragma unroll
    for (int o = 16; o > 0; o >>= 1) acc += __shfl_down_sync(0xffffffffu, acc, o);
    if (lane == 0) {
        float d = g_dis[j];
        float z = d * fmaf(d, g_p[j], acc) + g_c;
        out[warp] = 1.0f / (1.0f + expf(-z));
    }
}

// ---------------- launch ----------------
extern "C" void kernel_launch(void* const* d_in, const int* in_sizes, int n_in,
                              void* d_out, int out_size) {
    (void)in_sizes; (void)n_in; (void)out_size;
    const float* x    = (const float*)d_in[0];
    const int*   eidx = (const int*)  d_in[1];
    const int*   join = (const int*)  d_in[2];
    const float* ew   = (const float*)d_in[3];
    const float* W1   = (const float*)d_in[4];
    const float* b1   = (const float*)d_in[5];
    const float* W2   = (const float*)d_in[6];
    const float* b2   = (const float*)d_in[7];
    const float* Wl   = (const float*)d_in[8];
    const float* bl   = (const float*)d_in[9];
    float*       out  = (float*)d_out;

    const int* src = eidx;
    const int* dst = eidx + EE;

    static cudaStream_t sA = 0;
    static cudaEvent_t evRoot = 0, evA = 0;
    static bool inited = false;
    if (!inited) {
        cudaStreamCreateWithFlags(&sA, cudaStreamNonBlocking);
        cudaEventCreateWithFlags(&evRoot, cudaEventDisableTiming);
        cudaEventCreateWithFlags(&evA, cudaEventDisableTiming);
        cudaFuncSetAttribute(k_gemm1, cudaFuncAttributeMaxDynamicSharedMemorySize,
                             G1_SMEM_BYTES);
        inited = true;
    }

    const int g1_blocks = (NN + 127) / 128;           // 782

    cudaEventRecord(evRoot, 0);
    cudaStreamWaitEvent(sA, evRoot, 0);

    k_init  <<<(NN + 255) / 256, 256>>>(W2, b2, Wl, bl);           // #0 (B)
    k_hist  <<<EE / 256, 256>>>(dst, ew);                          // #1 (B)
    k_scan  <<<NSCANB, 256>>>();                                   // #2 (B)
    k_gemm1 <<<g1_blocks, 512, G1_SMEM_BYTES, sA>>>(x, W1);        // #3 (A) <- profiled
    k_fill  <<<EE / 256, 256>>>(src, dst, ew);                     // #4 (B)

    cudaEventRecord(evA, sA);
    cudaStreamWaitEvent(0, evA, 0);                                // join A -> B

    k_agg1q <<<(NN * 32 + 255) / 256, 256>>>(b1);                  // #5
    k_head  <<<(BJ * 32) / 256, 256>>>(join, out);                 // #6
}